// round 1
// baseline (speedup 1.0000x reference)
#include <cuda_runtime.h>
#include <cstddef>

// Problem constants
#define KB   1024          // batch
#define KL   50            // seq len
#define KE   64            // emb dim
#define KFV  4
#define KFH  16
#define KT   1024
#define KFEAT 1056         // FV*E + FH*L = 256 + 800

typedef unsigned long long u64;

// ---- scratch (static device globals; no runtime allocation) ----
__device__ float g_emb[KB * KL * KE];     // gathered item embeddings
__device__ float g_feat[KB * KFEAT];      // [out_v | out_h]
__device__ float g_x[KB * 128];           // [z | user_emb]

// ---- packed f32x2 helpers (Blackwell) ----
__device__ __forceinline__ u64 pk(float x, float y) {
    u64 r; asm("mov.b64 %0, {%1, %2};" : "=l"(r) : "f"(x), "f"(y)); return r;
}
__device__ __forceinline__ void upk(u64 u, float& x, float& y) {
    asm("mov.b64 {%0, %1}, %2;" : "=f"(x), "=f"(y) : "l"(u));
}
__device__ __forceinline__ u64 fma2(u64 a, u64 b, u64 c) {
    u64 d; asm("fma.rn.f32x2 %0, %1, %2, %3;" : "=l"(d) : "l"(a), "l"(b), "l"(c)); return d;
}

// ============================================================
// K1: gather item embeddings + vertical conv (out_v)
// grid = B blocks x 256 threads
// ============================================================
__global__ void k1_gather_outv(const int* __restrict__ seqs,
                               const float* __restrict__ itab,
                               const float* __restrict__ Wv,
                               const float* __restrict__ bv) {
    __shared__ float es[KL * KE];
    __shared__ float wv[KFV * KL];
    int b = blockIdx.x, tid = threadIdx.x;

    for (int idx = tid; idx < KL * KE; idx += 256) {
        int l = idx >> 6, e = idx & 63;
        int item = __ldg(&seqs[b * KL + l]);
        float v = __ldg(&itab[(size_t)item * KE + e]);
        es[idx] = v;
        g_emb[(size_t)b * KL * KE + idx] = v;
    }
    if (tid < KFV * KL) wv[tid] = Wv[tid];
    __syncthreads();

    // out_v[b,f,e] = sum_l emb[b,l,e] * Wv[f,l] + bv[f]   (256 outputs, 256 threads)
    int f = tid >> 6, e = tid & 63;
    float acc = __ldg(&bv[f]);
#pragma unroll
    for (int l = 0; l < KL; l++)
        acc = fmaf(es[l * KE + e], wv[f * KL + l], acc);
    g_feat[(size_t)b * KFEAT + f * KE + e] = acc;
}

// ============================================================
// K2: horizontal convs + relu + maxpool (the FLOP-heavy part)
// grid = (B, L) blocks x 512 threads; warp w handles filter f=w.
// lane owns e-pair (2*lane, 2*lane+1); packed f32x2 FMA.
// 8-wide sliding window of positions register-blocked.
// ============================================================
__global__ __launch_bounds__(512) void k2_conv(const float* __restrict__ Wh,
                                               const float* __restrict__ bh) {
    __shared__ float2 es[58 * 32];  // rows 50..57 zero padding
    int b = blockIdx.x, i = blockIdx.y;
    int tid = threadIdx.x, lane = tid & 31, f = tid >> 5;

    float* esf = (float*)es;
    for (int idx = tid; idx < 58 * 64; idx += 512)
        esf[idx] = (idx < KL * KE) ? g_emb[(size_t)b * KL * KE + idx] : 0.f;
    __syncthreads();

    int h = i + 1;
    int P = KL - h + 1;                 // valid positions
    const float2* wrow =
        (const float2*)(Wh + (size_t)(i * KFH + f) * KL * KE) + lane;  // +32 float2 per j

    float maxv = -3.4e38f;

    for (int p0 = 0; p0 < P; p0 += 8) {
        u64 acc[8], ew[8];
#pragma unroll
        for (int k = 0; k < 8; k++) {
            acc[k] = 0ULL;  // packed (0.f, 0.f)
            float2 v = es[(p0 + k) * 32 + lane];
            ew[k] = pk(v.x, v.y);
        }
        int j = 0;
        for (; j + 8 <= h; j += 8) {
#pragma unroll
            for (int jj = 0; jj < 8; jj++) {
                float2 wv2 = __ldg(wrow + (j + jj) * 32);
                u64 w = pk(wv2.x, wv2.y);
#pragma unroll
                for (int k = 0; k < 8; k++) acc[k] = fma2(ew[k], w, acc[k]);
#pragma unroll
                for (int k = 0; k < 7; k++) ew[k] = ew[k + 1];
                float2 nv = es[(p0 + j + jj + 8) * 32 + lane];  // max row 57 (padded)
                ew[7] = pk(nv.x, nv.y);
            }
        }
        for (; j < h; j++) {
            float2 wv2 = __ldg(wrow + j * 32);
            u64 w = pk(wv2.x, wv2.y);
#pragma unroll
            for (int k = 0; k < 8; k++) acc[k] = fma2(ew[k], w, acc[k]);
#pragma unroll
            for (int k = 0; k < 7; k++) ew[k] = ew[k + 1];
            float2 nv = es[(p0 + j + 8) * 32 + lane];
            ew[7] = pk(nv.x, nv.y);
        }
        // reduce each position across lanes, fold into running max
#pragma unroll
        for (int k = 0; k < 8; k++) {
            float x, y; upk(acc[k], x, y);
            float s = x + y;
#pragma unroll
            for (int off = 16; off; off >>= 1)
                s += __shfl_xor_sync(0xffffffffu, s, off);
            if (p0 + k < P) maxv = fmaxf(maxv, s);
        }
    }

    if (lane == 0) {
        float r = fmaxf(0.f, maxv + __ldg(&bh[i * KFH + f]));
        g_feat[(size_t)b * KFEAT + KFV * KE + i * KFH + f] = r;
    }
}

// ============================================================
// K3: z = relu(feat @ W1^T + b1); x = [z, user_emb]
// grid = B blocks x 256 threads
// ============================================================
__global__ void k3_dense(const float* __restrict__ W1,
                         const float* __restrict__ b1,
                         const int* __restrict__ uvar,
                         const float* __restrict__ utab) {
    __shared__ float fs[KFEAT];
    __shared__ float zs[64];
    int b = blockIdx.x, tid = threadIdx.x, lane = tid & 31, w = tid >> 5;

    for (int idx = tid; idx < KFEAT; idx += 256)
        fs[idx] = g_feat[(size_t)b * KFEAT + idx];
    __syncthreads();

#pragma unroll
    for (int q = 0; q < 8; q++) {
        int o = w * 8 + q;
        const float* wr = W1 + (size_t)o * KFEAT;
        float acc = 0.f;
        for (int kk = lane; kk < KFEAT; kk += 32)
            acc = fmaf(fs[kk], __ldg(&wr[kk]), acc);
#pragma unroll
        for (int off = 16; off; off >>= 1)
            acc += __shfl_xor_sync(0xffffffffu, acc, off);
        if (lane == 0) zs[o] = acc;
    }
    __syncthreads();

    if (tid < 64) {
        g_x[(size_t)b * 128 + tid] = fmaxf(0.f, zs[tid] + __ldg(&b1[tid]));
    } else if (tid < 128) {
        int u = __ldg(&uvar[b]);
        g_x[(size_t)b * 128 + tid] = __ldg(&utab[(size_t)u * 64 + (tid - 64)]);
    }
}

// ============================================================
// K4: res[b,t] = dot(W2_table[item], x[b]) + b2_table[item]
// grid = B blocks x 256 threads; warp per output, 2-way ILP
// ============================================================
__global__ void k4_score(const int* __restrict__ items,
                         const float* __restrict__ W2,
                         const float* __restrict__ b2t,
                         float* __restrict__ out) {
    int b = blockIdx.x, tid = threadIdx.x, lane = tid & 31, w = tid >> 5;
    float4 x = *(const float4*)&g_x[(size_t)b * 128 + lane * 4];
    const int* ib = items + (size_t)b * KT;
    float* ob = out + (size_t)b * KT;

    for (int t = w; t < KT; t += 16) {
        int i0 = __ldg(&ib[t]);
        int i1 = __ldg(&ib[t + 8]);
        float4 a0 = __ldg((const float4*)(W2 + (size_t)i0 * 128) + lane);
        float4 a1 = __ldg((const float4*)(W2 + (size_t)i1 * 128) + lane);
        float s0 = a0.x * x.x + a0.y * x.y + a0.z * x.z + a0.w * x.w;
        float s1 = a1.x * x.x + a1.y * x.y + a1.z * x.z + a1.w * x.w;
#pragma unroll
        for (int off = 16; off; off >>= 1) {
            s0 += __shfl_xor_sync(0xffffffffu, s0, off);
            s1 += __shfl_xor_sync(0xffffffffu, s1, off);
        }
        if (lane == 0) {
            ob[t]     = s0 + __ldg(&b2t[i0]);
            ob[t + 8] = s1 + __ldg(&b2t[i1]);
        }
    }
}

// ============================================================
// Launch
// Inputs (metadata order):
// 0 input_seqs (B,L) i32       1 items_to_predict (B,1,T) i32
// 2 user_var (B,) i32          3 user_table (50001,64) f32
// 4 item_table (200001,64) f32 5 Wv (4,1,50,1) f32
// 6 bv (4,) f32                7 Wh (50,16,50,64) f32
// 8 bh (50,16) f32             9 W1 (64,1056) f32
// 10 b1 (64,) f32              11 W2_table (200001,128) f32
// 12 b2_table (200001,1) f32
// ============================================================
extern "C" void kernel_launch(void* const* d_in, const int* in_sizes, int n_in,
                              void* d_out, int out_size) {
    const int*   seqs  = (const int*)d_in[0];
    const int*   items = (const int*)d_in[1];
    const int*   uvar  = (const int*)d_in[2];
    const float* utab  = (const float*)d_in[3];
    const float* itab  = (const float*)d_in[4];
    const float* Wv    = (const float*)d_in[5];
    const float* bv    = (const float*)d_in[6];
    const float* Wh    = (const float*)d_in[7];
    const float* bh    = (const float*)d_in[8];
    const float* W1    = (const float*)d_in[9];
    const float* b1    = (const float*)d_in[10];
    const float* W2    = (const float*)d_in[11];
    const float* b2t   = (const float*)d_in[12];
    float* out = (float*)d_out;

    k1_gather_outv<<<KB, 256>>>(seqs, itab, Wv, bv);
    k2_conv<<<dim3(KB, KL), 512>>>(Wh, bh);
    k3_dense<<<KB, 256>>>(W1, b1, uvar, utab);
    k4_score<<<KB, 256>>>(items, W2, b2t, out);
}

// round 2
// speedup vs baseline: 1.4724x; 1.4724x over previous
#include <cuda_runtime.h>
#include <cstddef>

// Problem constants
#define KB   1024          // batch
#define KL   50            // seq len
#define KE   64            // emb dim
#define KFV  4
#define KFH  16
#define KT   1024
#define KFEAT 1056         // FV*E + FH*L = 256 + 800

typedef unsigned long long u64;

// ---- scratch (static device globals; no runtime allocation) ----
__device__ float g_emb[KB * KL * KE];     // gathered item embeddings
__device__ float g_feat[KB * KFEAT];      // [out_v | out_h]
__device__ float g_x[KB * 128];           // [z | user_emb]

// ---- packed f32x2 helpers (Blackwell) ----
__device__ __forceinline__ u64 pk(float x, float y) {
    u64 r; asm("mov.b64 %0, {%1, %2};" : "=l"(r) : "f"(x), "f"(y)); return r;
}
__device__ __forceinline__ void upk(u64 u, float& x, float& y) {
    asm("mov.b64 {%0, %1}, %2;" : "=f"(x), "=f"(y) : "l"(u));
}
__device__ __forceinline__ u64 fma2(u64 a, u64 b, u64 c) {
    u64 d; asm("fma.rn.f32x2 %0, %1, %2, %3;" : "=l"(d) : "l"(a), "l"(b), "l"(c)); return d;
}

// ============================================================
// K1: gather item embeddings + vertical conv (out_v)
// ============================================================
__global__ void k1_gather_outv(const int* __restrict__ seqs,
                               const float* __restrict__ itab,
                               const float* __restrict__ Wv,
                               const float* __restrict__ bv) {
    __shared__ float es[KL * KE];
    __shared__ float wv[KFV * KL];
    int b = blockIdx.x, tid = threadIdx.x;

    for (int idx = tid; idx < KL * KE; idx += 256) {
        int l = idx >> 6, e = idx & 63;
        int item = __ldg(&seqs[b * KL + l]);
        float v = __ldg(&itab[(size_t)item * KE + e]);
        es[idx] = v;
        g_emb[(size_t)b * KL * KE + idx] = v;
    }
    if (tid < KFV * KL) wv[tid] = Wv[tid];
    __syncthreads();

    int f = tid >> 6, e = tid & 63;
    float acc = __ldg(&bv[f]);
#pragma unroll
    for (int l = 0; l < KL; l++)
        acc = fmaf(es[l * KE + e], wv[f * KL + l], acc);
    g_feat[(size_t)b * KFEAT + f * KE + e] = acc;
}

// ============================================================
// K2: horizontal convs + relu + maxpool
// grid = (B/2, L); block 512 = 16 warps; warp = filter f.
// Each block handles TWO batch rows (halves weight L2 traffic,
// doubles fma2 per weight load). Lane owns e-pair; 8 positions
// x 2 batches register-blocked; fast 16-value butterfly reduce.
// ============================================================
__global__ __launch_bounds__(512, 1) void k2_conv(const float* __restrict__ Wh,
                                                  const float* __restrict__ bh) {
    __shared__ float2 es[2][58][32];  // rows 50..57 zero padding
    int bp = blockIdx.x, i = blockIdx.y;
    int tid = threadIdx.x, lane = tid & 31, f = tid >> 5;
    int b0 = bp * 2;

    const float2* ge = (const float2*)g_emb;
    for (int idx = tid; idx < 2 * 58 * 32; idx += 512) {
        int bl = idx / (58 * 32);
        int rem = idx - bl * (58 * 32);
        int r = rem >> 5, c = rem & 31;
        float2 v = make_float2(0.f, 0.f);
        if (r < KL) v = ge[((size_t)(b0 + bl) * KL + r) * 32 + c];
        es[bl][r][c] = v;
    }
    __syncthreads();

    int h = i + 1;
    int P = KL - i;                 // valid positions
    const float2* wrow =
        (const float2*)(Wh + (size_t)(i * KFH + f) * KL * KE) + lane;

    // fixed per-lane (b, k) slot produced by the butterfly reduction
    int k_lane = ((lane >> 3) & 1) * 4 + ((lane >> 2) & 1) * 2 + ((lane >> 1) & 1);
    float maxv = -3.4e38f;

    for (int p0 = 0; p0 < P; p0 += 8) {
        u64 acc[2][8], ew[2][8];
#pragma unroll
        for (int bl = 0; bl < 2; bl++)
#pragma unroll
            for (int k = 0; k < 8; k++) {
                acc[bl][k] = 0ULL;
                float2 v = es[bl][p0 + k][lane];
                ew[bl][k] = pk(v.x, v.y);
            }
        int j = 0;
        for (; j + 8 <= h; j += 8) {
#pragma unroll
            for (int jj = 0; jj < 8; jj++) {
                float2 wv2 = __ldg(wrow + (j + jj) * 32);
                u64 w = pk(wv2.x, wv2.y);
#pragma unroll
                for (int bl = 0; bl < 2; bl++) {
#pragma unroll
                    for (int k = 0; k < 8; k++) acc[bl][k] = fma2(ew[bl][k], w, acc[bl][k]);
#pragma unroll
                    for (int k = 0; k < 7; k++) ew[bl][k] = ew[bl][k + 1];
                    float2 nv = es[bl][p0 + j + jj + 8][lane];
                    ew[bl][7] = pk(nv.x, nv.y);
                }
            }
        }
        for (; j < h; j++) {
            float2 wv2 = __ldg(wrow + j * 32);
            u64 w = pk(wv2.x, wv2.y);
#pragma unroll
            for (int bl = 0; bl < 2; bl++) {
#pragma unroll
                for (int k = 0; k < 8; k++) acc[bl][k] = fma2(ew[bl][k], w, acc[bl][k]);
#pragma unroll
                for (int k = 0; k < 7; k++) ew[bl][k] = ew[bl][k + 1];
                float2 nv = es[bl][p0 + j + 8][lane];
                ew[bl][7] = pk(nv.x, nv.y);
            }
        }

        // fold e-pairs, then reduce 16 values across 32 lanes in 16 shuffles
        float v[16];
#pragma unroll
        for (int bl = 0; bl < 2; bl++)
#pragma unroll
            for (int k = 0; k < 8; k++) {
                float x, y; upk(acc[bl][k], x, y);
                v[bl * 8 + k] = x + y;
            }
#pragma unroll
        for (int m = 16, half = 8; m >= 2; m >>= 1, half >>= 1) {
#pragma unroll
            for (int q = 0; q < 8; q++) {
                if (q >= half) break;
                bool hibit = (lane & m) != 0;
                float send = hibit ? v[q] : v[q + half];
                float recv = __shfl_xor_sync(0xffffffffu, send, m);
                v[q] = (hibit ? v[q + half] : v[q]) + recv;
            }
        }
        v[0] += __shfl_xor_sync(0xffffffffu, v[0], 1);
        // lane now holds full sum for (b = lane>>4, pos = p0 + k_lane)
        float s = (p0 + k_lane < P) ? v[0] : -3.4e38f;
        maxv = fmaxf(maxv, s);
    }

    // max over k within each 16-lane half (bits 8,4,2 index k; bit 1 dup)
#pragma unroll
    for (int m = 8; m >= 1; m >>= 1)
        maxv = fmaxf(maxv, __shfl_xor_sync(0xffffffffu, maxv, m));

    if ((lane & 15) == 0) {
        int bb = b0 + (lane >> 4);
        float r = fmaxf(0.f, maxv + __ldg(&bh[i * KFH + f]));
        g_feat[(size_t)bb * KFEAT + KFV * KE + i * KFH + f] = r;
    }
}

// ============================================================
// K3: z = relu(feat @ W1^T + b1); x = [z, user_emb]
// ============================================================
__global__ void k3_dense(const float* __restrict__ W1,
                         const float* __restrict__ b1,
                         const int* __restrict__ uvar,
                         const float* __restrict__ utab) {
    __shared__ float fs[KFEAT];
    __shared__ float zs[64];
    int b = blockIdx.x, tid = threadIdx.x, lane = tid & 31, w = tid >> 5;

    for (int idx = tid; idx < KFEAT; idx += 256)
        fs[idx] = g_feat[(size_t)b * KFEAT + idx];
    __syncthreads();

#pragma unroll
    for (int q = 0; q < 8; q++) {
        int o = w * 8 + q;
        const float* wr = W1 + (size_t)o * KFEAT;
        float acc = 0.f;
        for (int kk = lane; kk < KFEAT; kk += 32)
            acc = fmaf(fs[kk], __ldg(&wr[kk]), acc);
#pragma unroll
        for (int off = 16; off; off >>= 1)
            acc += __shfl_xor_sync(0xffffffffu, acc, off);
        if (lane == 0) zs[o] = acc;
    }
    __syncthreads();

    if (tid < 64) {
        g_x[(size_t)b * 128 + tid] = fmaxf(0.f, zs[tid] + __ldg(&b1[tid]));
    } else if (tid < 128) {
        int u = __ldg(&uvar[b]);
        g_x[(size_t)b * 128 + tid] = __ldg(&utab[(size_t)u * 64 + (tid - 64)]);
    }
}

// ============================================================
// K4: res[b,t] = dot(W2_table[item], x[b]) + b2_table[item]
// grid = B x 256 threads; warp handles 4 consecutive t (MLP=4),
// 6-shuffle 4-value butterfly reduction.
// ============================================================
__global__ void k4_score(const int* __restrict__ items,
                         const float* __restrict__ W2,
                         const float* __restrict__ b2t,
                         float* __restrict__ out) {
    int b = blockIdx.x, tid = threadIdx.x, lane = tid & 31, w = tid >> 5;
    float4 x = *(const float4*)&g_x[(size_t)b * 128 + lane * 4];
    const int* ib = items + (size_t)b * KT;
    float* ob = out + (size_t)b * KT;

    // which of the 4 t's this lane ends up owning after the butterfly
    int idx_lane = ((lane >> 4) & 1) * 2 + ((lane >> 3) & 1);

    for (int t = w * 4; t < KT; t += 32) {
        int i0 = __ldg(&ib[t]);
        int i1 = __ldg(&ib[t + 1]);
        int i2 = __ldg(&ib[t + 2]);
        int i3 = __ldg(&ib[t + 3]);
        float4 a0 = __ldg((const float4*)(W2 + (size_t)i0 * 128) + lane);
        float4 a1 = __ldg((const float4*)(W2 + (size_t)i1 * 128) + lane);
        float4 a2 = __ldg((const float4*)(W2 + (size_t)i2 * 128) + lane);
        float4 a3 = __ldg((const float4*)(W2 + (size_t)i3 * 128) + lane);
        float v[4];
        v[0] = a0.x * x.x + a0.y * x.y + a0.z * x.z + a0.w * x.w;
        v[1] = a1.x * x.x + a1.y * x.y + a1.z * x.z + a1.w * x.w;
        v[2] = a2.x * x.x + a2.y * x.y + a2.z * x.z + a2.w * x.w;
        v[3] = a3.x * x.x + a3.y * x.y + a3.z * x.z + a3.w * x.w;

        // 4-value butterfly: m=16 (half=2), m=8 (half=1), then dup bits 4,2,1
#pragma unroll
        for (int m = 16, half = 2; m >= 8; m >>= 1, half >>= 1) {
#pragma unroll
            for (int q = 0; q < 2; q++) {
                if (q >= half) break;
                bool hibit = (lane & m) != 0;
                float send = hibit ? v[q] : v[q + half];
                float recv = __shfl_xor_sync(0xffffffffu, send, m);
                v[q] = (hibit ? v[q + half] : v[q]) + recv;
            }
        }
        v[0] += __shfl_xor_sync(0xffffffffu, v[0], 4);
        v[0] += __shfl_xor_sync(0xffffffffu, v[0], 2);
        v[0] += __shfl_xor_sync(0xffffffffu, v[0], 1);
        // lane holds sum for t + idx_lane (idx = 2*b16 + b8)
        if ((lane & 7) == 0) {
            int ii = (idx_lane == 0) ? i0 : (idx_lane == 1) ? i1 : (idx_lane == 2) ? i2 : i3;
            ob[t + idx_lane] = v[0] + __ldg(&b2t[ii]);
        }
    }
}

// ============================================================
extern "C" void kernel_launch(void* const* d_in, const int* in_sizes, int n_in,
                              void* d_out, int out_size) {
    const int*   seqs  = (const int*)d_in[0];
    const int*   items = (const int*)d_in[1];
    const int*   uvar  = (const int*)d_in[2];
    const float* utab  = (const float*)d_in[3];
    const float* itab  = (const float*)d_in[4];
    const float* Wv    = (const float*)d_in[5];
    const float* bv    = (const float*)d_in[6];
    const float* Wh    = (const float*)d_in[7];
    const float* bh    = (const float*)d_in[8];
    const float* W1    = (const float*)d_in[9];
    const float* b1    = (const float*)d_in[10];
    const float* W2    = (const float*)d_in[11];
    const float* b2t   = (const float*)d_in[12];
    float* out = (float*)d_out;

    k1_gather_outv<<<KB, 256>>>(seqs, itab, Wv, bv);
    k2_conv<<<dim3(KB / 2, KL), 512>>>(Wh, bh);
    k3_dense<<<KB, 256>>>(W1, b1, uvar, utab);
    k4_score<<<KB, 256>>>(items, W2, b2t, out);
}

// round 3
// speedup vs baseline: 1.5962x; 1.0841x over previous
#include <cuda_runtime.h>
#include <cstddef>

// Problem constants
#define KB   1024          // batch
#define KL   50            // seq len
#define KE   64            // emb dim
#define KFV  4
#define KFH  16
#define KT   1024
#define KFEAT 1056         // FV*E + FH*L = 256 + 800

typedef unsigned long long u64;

// ---- scratch (static device globals; no runtime allocation) ----
__device__ float g_emb[KB * KL * KE];     // gathered item embeddings
__device__ float g_feat[KB * KFEAT];      // [out_v | out_h]
__device__ float g_x[KB * 128];           // [z | user_emb]

// ---- packed f32x2 helpers (Blackwell) ----
__device__ __forceinline__ u64 pk(float x, float y) {
    u64 r; asm("mov.b64 %0, {%1, %2};" : "=l"(r) : "f"(x), "f"(y)); return r;
}
__device__ __forceinline__ void upk(u64 u, float& x, float& y) {
    asm("mov.b64 {%0, %1}, %2;" : "=f"(x), "=f"(y) : "l"(u));
}
__device__ __forceinline__ u64 fma2(u64 a, u64 b, u64 c) {
    u64 d; asm("fma.rn.f32x2 %0, %1, %2, %3;" : "=l"(d) : "l"(a), "l"(b), "l"(c)); return d;
}

// ============================================================
// K1: gather item embeddings + vertical conv (out_v)
// ============================================================
__global__ void k1_gather_outv(const int* __restrict__ seqs,
                               const float* __restrict__ itab,
                               const float* __restrict__ Wv,
                               const float* __restrict__ bv) {
    __shared__ float es[KL * KE];
    __shared__ float wv[KFV * KL];
    int b = blockIdx.x, tid = threadIdx.x;

    for (int idx = tid; idx < KL * KE; idx += 256) {
        int l = idx >> 6, e = idx & 63;
        int item = __ldg(&seqs[b * KL + l]);
        float v = __ldg(&itab[(size_t)item * KE + e]);
        es[idx] = v;
        g_emb[(size_t)b * KL * KE + idx] = v;
    }
    if (tid < KFV * KL) wv[tid] = Wv[tid];
    __syncthreads();

    int f = tid >> 6, e = tid & 63;
    float acc = __ldg(&bv[f]);
#pragma unroll
    for (int l = 0; l < KL; l++)
        acc = fmaf(es[l * KE + e], wv[f * KL + l], acc);
    g_feat[(size_t)b * KFEAT + f * KE + e] = acc;
}

// ============================================================
// K2: horizontal convs + relu + maxpool
// grid = (B/2, L); block 512 = 16 warps; warp = filter f.
// Circular 4-slot register window with STATIC rotation
// ((jj+k)&3 is compile-time) -> zero register moves, 8
// independent FFMA2 chains. j-remainder handled by predicating
// the weight load to zero (e rows >= 50 are zero-padded, so
// extra j-steps are exact no-ops).
// ============================================================
__global__ __launch_bounds__(512, 2) void k2_conv(const float* __restrict__ Wh,
                                                  const float* __restrict__ bh) {
    __shared__ float2 es[2][58][32];  // rows 50..57 zero padding
    int bp = blockIdx.x, i = blockIdx.y;
    int tid = threadIdx.x, lane = tid & 31, f = tid >> 5;
    int b0 = bp * 2;

    const float2* ge = (const float2*)g_emb;
    for (int idx = tid; idx < 2 * 58 * 32; idx += 512) {
        int bl = idx / (58 * 32);
        int rem = idx - bl * (58 * 32);
        int r = rem >> 5, c = rem & 31;
        float2 v = make_float2(0.f, 0.f);
        if (r < KL) v = ge[((size_t)(b0 + bl) * KL + r) * 32 + c];
        es[bl][r][c] = v;
    }
    __syncthreads();

    int h = i + 1;
    int P = KL - i;                 // valid positions
    const float2* wrow =
        (const float2*)(Wh + (size_t)(i * KFH + f) * KL * KE) + lane;

    // per-lane smem base (u64 view of float2 rows)
    const u64* esu[2];
    esu[0] = (const u64*)&es[0][0][0] + lane;
    esu[1] = (const u64*)&es[1][0][0] + lane;

    // value owned by this lane after the 8-value butterfly:
    // bl = bit4, k = bit3*2 + bit2, bits 1..0 dup
    int k_lane = ((lane >> 3) & 1) * 2 + ((lane >> 2) & 1);
    float maxv = -3.4e38f;

    for (int p0 = 0; p0 < P; p0 += 4) {
        u64 acc[2][4], buf[2][4];
#pragma unroll
        for (int bl = 0; bl < 2; bl++)
#pragma unroll
            for (int k = 0; k < 4; k++) {
                acc[bl][k] = 0ULL;
                buf[bl][k] = esu[bl][(p0 + k) * 32];
            }

        for (int jb = 0; jb < h; jb += 4) {
#pragma unroll
            for (int jj = 0; jj < 4; jj++) {
                int j = jb + jj;
                u64 w = 0ULL;
                if (j < h) {
                    float2 wv2 = __ldg(wrow + j * 32);
                    w = pk(wv2.x, wv2.y);
                }
#pragma unroll
                for (int bl = 0; bl < 2; bl++) {
                    acc[bl][0] = fma2(buf[bl][(jj + 0) & 3], w, acc[bl][0]);
                    acc[bl][1] = fma2(buf[bl][(jj + 1) & 3], w, acc[bl][1]);
                    acc[bl][2] = fma2(buf[bl][(jj + 2) & 3], w, acc[bl][2]);
                    acc[bl][3] = fma2(buf[bl][(jj + 3) & 3], w, acc[bl][3]);
                }
                // refill the slot just vacated (k=0 use) with row p0+j+4 (<=56)
                buf[0][jj] = esu[0][(p0 + j + 4) * 32];
                buf[1][jj] = esu[1][(p0 + j + 4) * 32];
            }
        }

        // fold e-pairs, then reduce 8 values across 32 lanes in 7 shuffles
        float v[8];
#pragma unroll
        for (int bl = 0; bl < 2; bl++)
#pragma unroll
            for (int k = 0; k < 4; k++) {
                float x, y; upk(acc[bl][k], x, y);
                v[bl * 4 + k] = x + y;
            }
#pragma unroll
        for (int m = 16, half = 4; m >= 4; m >>= 1, half >>= 1) {
#pragma unroll
            for (int q = 0; q < 4; q++) {
                if (q >= half) break;
                bool hibit = (lane & m) != 0;
                float send = hibit ? v[q] : v[q + half];
                float recv = __shfl_xor_sync(0xffffffffu, send, m);
                v[q] = (hibit ? v[q + half] : v[q]) + recv;
            }
        }
        v[0] += __shfl_xor_sync(0xffffffffu, v[0], 2);
        v[0] += __shfl_xor_sync(0xffffffffu, v[0], 1);
        // lane holds full sum for (b = b0 + (lane>>4), pos = p0 + k_lane)
        float s = (p0 + k_lane < P) ? v[0] : -3.4e38f;
        maxv = fmaxf(maxv, s);
    }

    // max over k (lane bits 3,2) within each 16-lane half; bits 1,0 dup
#pragma unroll
    for (int m = 8; m >= 1; m >>= 1)
        maxv = fmaxf(maxv, __shfl_xor_sync(0xffffffffu, maxv, m));

    if ((lane & 15) == 0) {
        int bb = b0 + (lane >> 4);
        float r = fmaxf(0.f, maxv + __ldg(&bh[i * KFH + f]));
        g_feat[(size_t)bb * KFEAT + KFV * KE + i * KFH + f] = r;
    }
}

// ============================================================
// K3: z = relu(feat @ W1^T + b1); x = [z, user_emb]
// ============================================================
__global__ void k3_dense(const float* __restrict__ W1,
                         const float* __restrict__ b1,
                         const int* __restrict__ uvar,
                         const float* __restrict__ utab) {
    __shared__ float fs[KFEAT];
    __shared__ float zs[64];
    int b = blockIdx.x, tid = threadIdx.x, lane = tid & 31, w = tid >> 5;

    for (int idx = tid; idx < KFEAT; idx += 256)
        fs[idx] = g_feat[(size_t)b * KFEAT + idx];
    __syncthreads();

#pragma unroll
    for (int q = 0; q < 8; q++) {
        int o = w * 8 + q;
        const float* wr = W1 + (size_t)o * KFEAT;
        float acc = 0.f;
        for (int kk = lane; kk < KFEAT; kk += 32)
            acc = fmaf(fs[kk], __ldg(&wr[kk]), acc);
#pragma unroll
        for (int off = 16; off; off >>= 1)
            acc += __shfl_xor_sync(0xffffffffu, acc, off);
        if (lane == 0) zs[o] = acc;
    }
    __syncthreads();

    if (tid < 64) {
        g_x[(size_t)b * 128 + tid] = fmaxf(0.f, zs[tid] + __ldg(&b1[tid]));
    } else if (tid < 128) {
        int u = __ldg(&uvar[b]);
        g_x[(size_t)b * 128 + tid] = __ldg(&utab[(size_t)u * 64 + (tid - 64)]);
    }
}

// ============================================================
// K4: res[b,t] = dot(W2_table[item], x[b]) + b2_table[item]
// grid = B x 256 threads; warp handles 4 consecutive t (MLP=4),
// 6-shuffle 4-value butterfly reduction.
// ============================================================
__global__ void k4_score(const int* __restrict__ items,
                         const float* __restrict__ W2,
                         const float* __restrict__ b2t,
                         float* __restrict__ out) {
    int b = blockIdx.x, tid = threadIdx.x, lane = tid & 31, w = tid >> 5;
    float4 x = *(const float4*)&g_x[(size_t)b * 128 + lane * 4];
    const int* ib = items + (size_t)b * KT;
    float* ob = out + (size_t)b * KT;

    int idx_lane = ((lane >> 4) & 1) * 2 + ((lane >> 3) & 1);

    for (int t = w * 4; t < KT; t += 32) {
        int i0 = __ldg(&ib[t]);
        int i1 = __ldg(&ib[t + 1]);
        int i2 = __ldg(&ib[t + 2]);
        int i3 = __ldg(&ib[t + 3]);
        float4 a0 = __ldg((const float4*)(W2 + (size_t)i0 * 128) + lane);
        float4 a1 = __ldg((const float4*)(W2 + (size_t)i1 * 128) + lane);
        float4 a2 = __ldg((const float4*)(W2 + (size_t)i2 * 128) + lane);
        float4 a3 = __ldg((const float4*)(W2 + (size_t)i3 * 128) + lane);
        float v[4];
        v[0] = a0.x * x.x + a0.y * x.y + a0.z * x.z + a0.w * x.w;
        v[1] = a1.x * x.x + a1.y * x.y + a1.z * x.z + a1.w * x.w;
        v[2] = a2.x * x.x + a2.y * x.y + a2.z * x.z + a2.w * x.w;
        v[3] = a3.x * x.x + a3.y * x.y + a3.z * x.z + a3.w * x.w;

#pragma unroll
        for (int m = 16, half = 2; m >= 8; m >>= 1, half >>= 1) {
#pragma unroll
            for (int q = 0; q < 2; q++) {
                if (q >= half) break;
                bool hibit = (lane & m) != 0;
                float send = hibit ? v[q] : v[q + half];
                float recv = __shfl_xor_sync(0xffffffffu, send, m);
                v[q] = (hibit ? v[q + half] : v[q]) + recv;
            }
        }
        v[0] += __shfl_xor_sync(0xffffffffu, v[0], 4);
        v[0] += __shfl_xor_sync(0xffffffffu, v[0], 2);
        v[0] += __shfl_xor_sync(0xffffffffu, v[0], 1);
        if ((lane & 7) == 0) {
            int ii = (idx_lane == 0) ? i0 : (idx_lane == 1) ? i1 : (idx_lane == 2) ? i2 : i3;
            ob[t + idx_lane] = v[0] + __ldg(&b2t[ii]);
        }
    }
}

// ============================================================
extern "C" void kernel_launch(void* const* d_in, const int* in_sizes, int n_in,
                              void* d_out, int out_size) {
    const int*   seqs  = (const int*)d_in[0];
    const int*   items = (const int*)d_in[1];
    const int*   uvar  = (const int*)d_in[2];
    const float* utab  = (const float*)d_in[3];
    const float* itab  = (const float*)d_in[4];
    const float* Wv    = (const float*)d_in[5];
    const float* bv    = (const float*)d_in[6];
    const float* Wh    = (const float*)d_in[7];
    const float* bh    = (const float*)d_in[8];
    const float* W1    = (const float*)d_in[9];
    const float* b1    = (const float*)d_in[10];
    const float* W2    = (const float*)d_in[11];
    const float* b2t   = (const float*)d_in[12];
    float* out = (float*)d_out;

    k1_gather_outv<<<KB, 256>>>(seqs, itab, Wv, bv);
    k2_conv<<<dim3(KB / 2, KL), 512>>>(Wh, bh);
    k3_dense<<<KB, 256>>>(W1, b1, uvar, utab);
    k4_score<<<KB, 256>>>(items, W2, b2t, out);
}

// round 5
// speedup vs baseline: 2.6832x; 1.6810x over previous
#include <cuda_runtime.h>
#include <cstddef>

// Problem constants
#define KB   1024          // batch
#define KL   50            // seq len
#define KE   64            // emb dim
#define KFV  4
#define KFH  16
#define KT   1024
#define KFEAT 1056         // FV*E + FH*L

typedef unsigned int u32;

// ---- scratch (static device globals) ----
__device__ float g_emb[KB * KL * KE];     // gathered item embeddings (fp32)
__device__ float g_feat[KB * KFEAT];      // [out_v | out_h]
__device__ float g_x[KB * 128];           // [z | user_emb]

__device__ __forceinline__ u32 cvt_tf32(float x) {
    u32 r; asm("cvt.rna.tf32.f32 %0, %1;" : "=r"(r) : "f"(x)); return r;
}

// ============================================================
// K1: gather item embeddings + vertical conv (out_v)
// ============================================================
__global__ void k1_gather_outv(const int* __restrict__ seqs,
                               const float* __restrict__ itab,
                               const float* __restrict__ Wv,
                               const float* __restrict__ bv) {
    __shared__ float es[KL * KE];
    __shared__ float wv[KFV * KL];
    int b = blockIdx.x, tid = threadIdx.x;

    for (int idx = tid; idx < KL * KE; idx += 256) {
        int l = idx >> 6, e = idx & 63;
        int item = __ldg(&seqs[b * KL + l]);
        float v = __ldg(&itab[(size_t)item * KE + e]);
        es[idx] = v;
        g_emb[(size_t)b * KL * KE + idx] = v;
    }
    if (tid < KFV * KL) wv[tid] = Wv[tid];
    __syncthreads();

    int f = tid >> 6, e = tid & 63;
    float acc = __ldg(&bv[f]);
#pragma unroll
    for (int l = 0; l < KL; l++)
        acc = fmaf(es[l * KE + e], wv[f * KL + l], acc);
    g_feat[(size_t)b * KFEAT + f * KE + e] = acc;
}

// ============================================================
// K2: horizontal convs via tf32 mma.sync (tensor pipe)
// grid = (B/2, L); 256 threads = 8 warps.
// Warp w: mtile = w>>1 (16 positions), nhalf = w&1 (8 filters),
// both batches of the pair (shared B fragments).
// A[p][j*64+e] = es[p+j][e]  (smem, stride 68, zero-padded rows)
// B[j*64+e][f] = Wh[i][f][j][e] staged per-j (double-buffered).
// Positions p >= P produce garbage that is discarded at max time.
// ============================================================
__global__ __launch_bounds__(256) void k2_conv(const float* __restrict__ Wh,
                                               const float* __restrict__ bh) {
    __shared__ __align__(16) u32 es[2][65][68];   // tf32 bits, rows >= 50 zero
    __shared__ __align__(16) u32 ws[2][16][68];   // [buf][f][j-local*64+e... 64 used]
    __shared__ float red[2][4][16];

    int bp = blockIdx.x, i = blockIdx.y;
    int tid = threadIdx.x, lane = tid & 31, w = tid >> 5;
    int b0 = bp * 2;
    int h = i + 1, P = KL - i;
    int ntiles = (P + 15) >> 4;

    // zero es + init red
    {
        uint4* z4 = (uint4*)&es[0][0][0];
        const uint4 zz = make_uint4(0u, 0u, 0u, 0u);
        for (int idx = tid; idx < 2 * 65 * 17; idx += 256) z4[idx] = zz;
        if (tid < 128) (&red[0][0][0])[tid] = -3.4e38f;
    }
    __syncthreads();

    // fill rows < 50 with tf32-converted embeddings (float4-wide)
    {
        const float4* ge4 = (const float4*)g_emb;
        for (int idx = tid; idx < 2 * 50 * 16; idx += 256) {
            int bl = idx / 800;
            int rem = idx - bl * 800;
            int r = rem >> 4, e4 = (rem & 15) << 2;
            float4 v = ge4[((size_t)(b0 + bl) * KL + r) * 16 + (rem & 15)];
            *(uint4*)&es[bl][r][e4] =
                make_uint4(cvt_tf32(v.x), cvt_tf32(v.y), cvt_tf32(v.z), cvt_tf32(v.w));
        }
    }

    // stage weights for j = 0 into ws[0]
    {
        int f = tid >> 4, p4 = (tid & 15) << 2;
        float4 wv = __ldg((const float4*)(Wh + (size_t)(i * KFH + f) * (KL * KE) + p4));
        *(uint4*)&ws[0][f][p4] =
            make_uint4(cvt_tf32(wv.x), cvt_tf32(wv.y), cvt_tf32(wv.z), cvt_tf32(wv.w));
    }
    __syncthreads();

    int mtile = w >> 1, nhalf = w & 1;
    bool active = (mtile < ntiles);
    int g = lane >> 2, t = lane & 3;
    int R0 = mtile * 16 + g;

    float c0[2][4];
#pragma unroll
    for (int bl = 0; bl < 2; bl++)
#pragma unroll
        for (int q = 0; q < 4; q++) c0[bl][q] = 0.f;

    int buf = 0;
    for (int j = 0; j < h; j++) {
        // stage j+1 into the other buffer (all threads)
        if (j + 1 < h) {
            int f = tid >> 4, p4 = (tid & 15) << 2;
            float4 wv = __ldg((const float4*)(Wh + (size_t)(i * KFH + f) * (KL * KE)
                                              + (j + 1) * KE + p4));
            *(uint4*)&ws[buf ^ 1][f][p4] =
                make_uint4(cvt_tf32(wv.x), cvt_tf32(wv.y), cvt_tf32(wv.z), cvt_tf32(wv.w));
        }
        if (active) {
            const u32* a0p = &es[0][R0 + j][t];
            const u32* a1p = &es[1][R0 + j][t];
            const u32* bpt = &ws[buf][nhalf * 8 + g][t];
#pragma unroll
            for (int s = 0; s < 8; s++) {
                u32 br0 = bpt[s * 8], br1 = bpt[s * 8 + 4];
                u32 a0 = a0p[s * 8], a1 = a0p[8 * 68 + s * 8];
                u32 a2 = a0p[s * 8 + 4], a3 = a0p[8 * 68 + s * 8 + 4];
                asm volatile(
                    "mma.sync.aligned.m16n8k8.row.col.f32.tf32.tf32.f32 "
                    "{%0,%1,%2,%3}, {%4,%5,%6,%7}, {%8,%9}, {%0,%1,%2,%3};"
                    : "+f"(c0[0][0]), "+f"(c0[0][1]), "+f"(c0[0][2]), "+f"(c0[0][3])
                    : "r"(a0), "r"(a1), "r"(a2), "r"(a3), "r"(br0), "r"(br1));
                u32 d0 = a1p[s * 8], d1 = a1p[8 * 68 + s * 8];
                u32 d2 = a1p[s * 8 + 4], d3 = a1p[8 * 68 + s * 8 + 4];
                asm volatile(
                    "mma.sync.aligned.m16n8k8.row.col.f32.tf32.tf32.f32 "
                    "{%0,%1,%2,%3}, {%4,%5,%6,%7}, {%8,%9}, {%0,%1,%2,%3};"
                    : "+f"(c0[1][0]), "+f"(c0[1][1]), "+f"(c0[1][2]), "+f"(c0[1][3])
                    : "r"(d0), "r"(d1), "r"(d2), "r"(d3), "r"(br0), "r"(br1));
            }
        }
        __syncthreads();
        buf ^= 1;
    }

    // epilogue: max over valid positions, per filter
    if (active) {
        int p0 = mtile * 16;
#pragma unroll
        for (int bl = 0; bl < 2; bl++) {
            bool vlo = (p0 + g < P), vhi = (p0 + g + 8 < P);
            float v0 = vlo ? c0[bl][0] : -3.4e38f;
            float v1 = vlo ? c0[bl][1] : -3.4e38f;
            float v2 = vhi ? c0[bl][2] : -3.4e38f;
            float v3 = vhi ? c0[bl][3] : -3.4e38f;
            float m0 = fmaxf(v0, v2), m1 = fmaxf(v1, v3);
#pragma unroll
            for (int off = 4; off <= 16; off <<= 1) {
                m0 = fmaxf(m0, __shfl_xor_sync(0xffffffffu, m0, off));
                m1 = fmaxf(m1, __shfl_xor_sync(0xffffffffu, m1, off));
            }
            if (lane < 4) {
                red[bl][mtile][nhalf * 8 + 2 * lane]     = m0;
                red[bl][mtile][nhalf * 8 + 2 * lane + 1] = m1;
            }
        }
    }
    __syncthreads();
    if (tid < 32) {
        int bl = tid >> 4, f = tid & 15;
        float m = fmaxf(fmaxf(red[bl][0][f], red[bl][1][f]),
                        fmaxf(red[bl][2][f], red[bl][3][f]));
        float r = fmaxf(0.f, m + __ldg(&bh[i * KFH + f]));
        g_feat[(size_t)(b0 + bl) * KFEAT + KFV * KE + i * KFH + f] = r;
    }
}

// ============================================================
// K3: z = relu(feat @ W1^T + b1); x = [z, user_emb]
// ============================================================
__global__ void k3_dense(const float* __restrict__ W1,
                         const float* __restrict__ b1,
                         const int* __restrict__ uvar,
                         const float* __restrict__ utab) {
    __shared__ float fs[KFEAT];
    __shared__ float zs[64];
    int b = blockIdx.x, tid = threadIdx.x, lane = tid & 31, w = tid >> 5;

    for (int idx = tid; idx < KFEAT; idx += 256)
        fs[idx] = g_feat[(size_t)b * KFEAT + idx];
    __syncthreads();

#pragma unroll
    for (int q = 0; q < 8; q++) {
        int o = w * 8 + q;
        const float* wr = W1 + (size_t)o * KFEAT;
        float acc = 0.f;
        for (int kk = lane; kk < KFEAT; kk += 32)
            acc = fmaf(fs[kk], __ldg(&wr[kk]), acc);
#pragma unroll
        for (int off = 16; off; off >>= 1)
            acc += __shfl_xor_sync(0xffffffffu, acc, off);
        if (lane == 0) zs[o] = acc;
    }
    __syncthreads();

    if (tid < 64) {
        g_x[(size_t)b * 128 + tid] = fmaxf(0.f, zs[tid] + __ldg(&b1[tid]));
    } else if (tid < 128) {
        int u = __ldg(&uvar[b]);
        g_x[(size_t)b * 128 + tid] = __ldg(&utab[(size_t)u * 64 + (tid - 64)]);
    }
}

// ============================================================
// K4: res[b,t] = dot(W2_table[item], x[b]) + b2_table[item]
// ============================================================
__global__ void k4_score(const int* __restrict__ items,
                         const float* __restrict__ W2,
                         const float* __restrict__ b2t,
                         float* __restrict__ out) {
    int b = blockIdx.x, tid = threadIdx.x, lane = tid & 31, w = tid >> 5;
    float4 x = *(const float4*)&g_x[(size_t)b * 128 + lane * 4];
    const int* ib = items + (size_t)b * KT;
    float* ob = out + (size_t)b * KT;

    int idx_lane = ((lane >> 4) & 1) * 2 + ((lane >> 3) & 1);

    for (int t = w * 4; t < KT; t += 32) {
        int i0 = __ldg(&ib[t]);
        int i1 = __ldg(&ib[t + 1]);
        int i2 = __ldg(&ib[t + 2]);
        int i3 = __ldg(&ib[t + 3]);
        float4 a0 = __ldg((const float4*)(W2 + (size_t)i0 * 128) + lane);
        float4 a1 = __ldg((const float4*)(W2 + (size_t)i1 * 128) + lane);
        float4 a2 = __ldg((const float4*)(W2 + (size_t)i2 * 128) + lane);
        float4 a3 = __ldg((const float4*)(W2 + (size_t)i3 * 128) + lane);
        float v[4];
        v[0] = a0.x * x.x + a0.y * x.y + a0.z * x.z + a0.w * x.w;
        v[1] = a1.x * x.x + a1.y * x.y + a1.z * x.z + a1.w * x.w;
        v[2] = a2.x * x.x + a2.y * x.y + a2.z * x.z + a2.w * x.w;
        v[3] = a3.x * x.x + a3.y * x.y + a3.z * x.z + a3.w * x.w;

#pragma unroll
        for (int m = 16, half = 2; m >= 8; m >>= 1, half >>= 1) {
#pragma unroll
            for (int q = 0; q < 2; q++) {
                if (q >= half) break;
                bool hibit = (lane & m) != 0;
                float send = hibit ? v[q] : v[q + half];
                float recv = __shfl_xor_sync(0xffffffffu, send, m);
                v[q] = (hibit ? v[q + half] : v[q]) + recv;
            }
        }
        v[0] += __shfl_xor_sync(0xffffffffu, v[0], 4);
        v[0] += __shfl_xor_sync(0xffffffffu, v[0], 2);
        v[0] += __shfl_xor_sync(0xffffffffu, v[0], 1);
        if ((lane & 7) == 0) {
            int ii = (idx_lane == 0) ? i0 : (idx_lane == 1) ? i1 : (idx_lane == 2) ? i2 : i3;
            ob[t + idx_lane] = v[0] + __ldg(&b2t[ii]);
        }
    }
}

// ============================================================
extern "C" void kernel_launch(void* const* d_in, const int* in_sizes, int n_in,
                              void* d_out, int out_size) {
    const int*   seqs  = (const int*)d_in[0];
    const int*   items = (const int*)d_in[1];
    const int*   uvar  = (const int*)d_in[2];
    const float* utab  = (const float*)d_in[3];
    const float* itab  = (const float*)d_in[4];
    const float* Wv    = (const float*)d_in[5];
    const float* bv    = (const float*)d_in[6];
    const float* Wh    = (const float*)d_in[7];
    const float* bh    = (const float*)d_in[8];
    const float* W1    = (const float*)d_in[9];
    const float* b1    = (const float*)d_in[10];
    const float* W2    = (const float*)d_in[11];
    const float* b2t   = (const float*)d_in[12];
    float* out = (float*)d_out;

    k1_gather_outv<<<KB, 256>>>(seqs, itab, Wv, bv);
    k2_conv<<<dim3(KB / 2, KL), 256>>>(Wh, bh);
    k3_dense<<<KB, 256>>>(W1, b1, uvar, utab);
    k4_score<<<KB, 256>>>(items, W2, b2t, out);
}